// round 8
// baseline (speedup 1.0000x reference)
#include <cuda_runtime.h>
#include <cuda_fp16.h>
#include <cstdint>

// ----------------------------------------------------------------------------
// GroupedLinear: out[t,n] = sum_k inp[t,k] * weight[e,n,k],  e = t / 2048
// Base-ISA path (no tcgen05 on plain sm_103 target).
// GEMM at legacy-HMMA floor (~280 TF/s). R7: hide fp32->fp16 conversion
// (156us serial) under the GEMM via 2 converter warps per CTA:
//  - upfront kernel converts expert 0 (A tokens 0-2047 + B rows 0-4095)
//  - CTAs bx<128 (wave-1 resident) convert experts 1..7 with spare DRAM BW
//  - consumers of expert e>=1 spin on cnt[e]==256 before their prologue
// GEMM: mma.sync.m16n8k16.f16 + ldmatrix + cp.async 3-stage pipeline.
// ----------------------------------------------------------------------------

#define E_EXPERTS 8
#define DIN 4096
#define DOUT 4096
#define T_TOK 16384
#define ROWBYTES (DIN * 2)     // 8192 bytes per fp16 scratch row

#define CTA_M 256
#define CTA_N 128
#define NCHUNKS 128            // 4096 / 32 K-chunks
#define THREADS 256            // tensor threads (8 warps)
#define THREADS_TOT 320        // + 2 converter warps
#define STAGES 3

#define CONV_CTAS 128          // converter CTAs (all wave-1 resident)
#define ROWS_PER_CTA 48        // 6144 rows per bundle / 128 CTAs
#define ROWS_PER_WARP 24
#define CNT_TARGET 256u        // 128 CTAs x 2 warps

#define SROW 80                                 // padded smem row stride (bytes)
#define A_STAGE_BYTES (CTA_M * SROW)            // 20480
#define B_STAGE_BYTES (CTA_N * SROW)            // 10240
#define STAGE_BYTES (A_STAGE_BYTES + B_STAGE_BYTES)  // 30720
#define SMEM_BYTES (STAGES * STAGE_BYTES)       // 92160

__device__ __half g_A[(size_t)T_TOK * DIN];                 // 128 MB
__device__ __half g_B[(size_t)E_EXPERTS * DOUT * DIN];      // 256 MB
__device__ unsigned g_cnt[E_EXPERTS];                       // bundle progress

// ---------------- low-level helpers -----------------------------------------

__device__ __forceinline__ uint32_t smem_to_u32(const void* smem_ptr) {
    uint32_t addr;
    asm("{ .reg .u64 tmp; cvta.to.shared.u64 tmp, %1; cvt.u32.u64 %0, tmp; }"
        : "=r"(addr) : "l"(smem_ptr));
    return addr;
}

__device__ __forceinline__ void cp16(uint32_t s, const void* g) {
    asm volatile("cp.async.cg.shared.global [%0], [%1], 16;"
                 :: "r"(s), "l"(g) : "memory");
}
__device__ __forceinline__ void cp_commit() {
    asm volatile("cp.async.commit_group;" ::: "memory");
}
#define CP_WAIT(n) asm volatile("cp.async.wait_group %0;" :: "n"(n) : "memory")

// Named barrier: tensor warps only (threads 0..255). Converter warps skip.
#define BAR_TENSOR() asm volatile("bar.sync 1, 256;" ::: "memory")

__device__ __forceinline__ void ldsm_x4(uint32_t* r, uint32_t addr) {
    asm volatile("ldmatrix.sync.aligned.m8n8.x4.shared.b16 {%0,%1,%2,%3}, [%4];"
                 : "=r"(r[0]), "=r"(r[1]), "=r"(r[2]), "=r"(r[3]) : "r"(addr));
}

__device__ __forceinline__ void mma_16816(float* d, const uint32_t* a,
                                          uint32_t b0, uint32_t b1) {
    asm volatile(
        "mma.sync.aligned.m16n8k16.row.col.f32.f16.f16.f32 "
        "{%0,%1,%2,%3}, {%4,%5,%6,%7}, {%8,%9}, {%0,%1,%2,%3};"
        : "+f"(d[0]), "+f"(d[1]), "+f"(d[2]), "+f"(d[3])
        : "r"(a[0]), "r"(a[1]), "r"(a[2]), "r"(a[3]), "r"(b0), "r"(b1));
}

__device__ __forceinline__ uint2 pack_half4(float4 v) {
    union { __half h[4]; uint2 u; } H;
    H.h[0] = __float2half_rn(v.x);
    H.h[1] = __float2half_rn(v.y);
    H.h[2] = __float2half_rn(v.z);
    H.h[3] = __float2half_rn(v.w);
    return H.u;
}

// ---------------- upfront kernel: expert 0 conversion + counter reset --------
// 6144 blocks: b < 2048 -> A token row b; else B row (b-2048). One 4096-float
// row per block, 4 x float4 per thread (MLP=4, warp-contiguous 512B).

__global__ void __launch_bounds__(256) conv0_kernel(const float* __restrict__ inp,
                                                    const float* __restrict__ w) {
    if (blockIdx.x == 0 && threadIdx.x < E_EXPERTS) g_cnt[threadIdx.x] = 0u;

    const int b = blockIdx.x;
    const int tid = threadIdx.x;
    const float4* src;
    uint2* dst;
    if (b < 2048) {
        src = (const float4*)(inp + (size_t)b * DIN);
        dst = (uint2*)(g_A + (size_t)b * DIN);
    } else {
        const size_t r = (size_t)(b - 2048);
        src = (const float4*)(w + r * DIN);
        dst = (uint2*)(g_B + r * DIN);
    }
#pragma unroll
    for (int i = 0; i < 4; ++i)
        dst[tid + i * 256] = pack_half4(__ldg(src + tid + i * 256));
}

// ---------------- GEMM kernel (+ converter warps) ----------------------------

__global__ void __launch_bounds__(THREADS_TOT, 1) gemm_kernel(
    const float* __restrict__ inp, const float* __restrict__ w,
    float* __restrict__ out)
{
    extern __shared__ char smem[];
    const int tid = threadIdx.x;
    const int bx = blockIdx.x;

    // ---------------- converter warps (tid 256..319) ----------------
    if (tid >= THREADS) {
        if (bx < CONV_CTAS) {
            const int cw = (tid - THREADS) >> 5;    // 0 or 1
            const int lane = tid & 31;
            const int rbase = bx * ROWS_PER_CTA + cw * ROWS_PER_WARP;
#pragma unroll 1
            for (int e = 1; e < E_EXPERTS; ++e) {
#pragma unroll 1
                for (int r = 0; r < ROWS_PER_WARP; ++r) {
                    const int row = rbase + r;     // 0..6143 within bundle
                    const float4* src;
                    uint2* dst;
                    if (row < 2048) {              // A share of bundle e
                        const size_t t = (size_t)e * 2048 + row;
                        src = (const float4*)(inp + t * DIN);
                        dst = (uint2*)(g_A + t * DIN);
                    } else {                       // B share of bundle e
                        const size_t br = (size_t)e * DOUT + (row - 2048);
                        src = (const float4*)(w + br * DIN);
                        dst = (uint2*)(g_B + br * DIN);
                    }
#pragma unroll 4
                    for (int j = 0; j < 32; ++j)
                        dst[lane + j * 32] = pack_half4(__ldg(src + lane + j * 32));
                }
                __threadfence();                   // release stores of bundle e
                if (lane == 0) atomicAdd(&g_cnt[e], 1u);
            }
        }
        return;
    }

    // ---------------- tensor warps (tid 0..255) ----------------
    const uint32_t smem_u32 = smem_to_u32(smem);
    const int wid = tid >> 5;
    const int lid = tid & 31;

    // Tile decode: N-fastest so concurrent CTAs share A strips + expert B in L2
    const int n_tile = bx & 31;           // 32 N-tiles of 128
    const int m_tile = bx >> 5;           // 64 M-tiles of 256
    const int e = m_tile >> 3;            // 2048 tokens / 256 rows = 8 m-tiles

    // Wait for this expert's bundle (expert 0 converted upfront).
    if (e > 0 && tid == 0) {
        volatile unsigned* p = &g_cnt[e];
        while (*p < CNT_TARGET) __nanosleep(256);
        __threadfence();                  // acquire
    }
    BAR_TENSOR();

    const char* Abase = (const char*)(g_A + (size_t)(m_tile * CTA_M) * DIN);
    const char* Bbase = (const char*)(g_B + ((size_t)e * DOUT +
                                             (size_t)n_tile * CTA_N) * DIN);

    uint32_t sA[STAGES], sB[STAGES];
#pragma unroll
    for (int s = 0; s < STAGES; ++s) {
        sA[s] = smem_u32 + s * STAGE_BYTES;
        sB[s] = sA[s] + A_STAGE_BYTES;
    }

    // A: 256 rows x 4 groups(16B) = 1024 cp; B: 128 x 4 = 512 cp; 6 per thread.
    const int l_row_a = tid >> 2;         // rows tid/4, tid/4+64, ...
    const int l_grp   = (tid & 3) * 16;   // byte group within 64B chunk

#define ISSUE_STAGE(stg, c) do {                                              \
        const char* aG_ = Abase + (size_t)(c) * 64;                           \
        const char* bG_ = Bbase + (size_t)(c) * 64;                           \
        _Pragma("unroll")                                                     \
        for (int i_ = 0; i_ < 4; ++i_) {                                      \
            int row_ = l_row_a + i_ * 64;                                     \
            cp16(sA[stg] + row_ * SROW + l_grp,                               \
                 aG_ + (size_t)row_ * ROWBYTES + l_grp);                      \
        }                                                                     \
        _Pragma("unroll")                                                     \
        for (int i_ = 0; i_ < 2; ++i_) {                                      \
            int row_ = l_row_a + i_ * 64;                                     \
            cp16(sB[stg] + row_ * SROW + l_grp,                               \
                 bG_ + (size_t)row_ * ROWBYTES + l_grp);                      \
        }                                                                     \
    } while (0)

    // Warp layout: 4(M) x 2(N); warp tile 64x64.
    const int wm = wid >> 1;
    const int wn = wid & 1;

    // ldmatrix lane addressing (non-trans, both operands K-major)
    const int lm_row = lid & 15;
    const int lm_col = (lid >> 4) * 16;

    float acc[4][8][4];
#pragma unroll
    for (int i = 0; i < 4; ++i)
#pragma unroll
        for (int j = 0; j < 8; ++j)
#pragma unroll
            for (int q = 0; q < 4; ++q) acc[i][j][q] = 0.0f;

    // Prologue: issue 2 stages
    ISSUE_STAGE(0, 0); cp_commit();
    ISSUE_STAGE(1, 1); cp_commit();

#pragma unroll 1
    for (int c = 0; c < NCHUNKS; ++c) {
        CP_WAIT(1);
        BAR_TENSOR();

        if (c + 2 < NCHUNKS) {
            int stg = (c + 2) % STAGES;
            ISSUE_STAGE(stg, c + 2);
        }
        cp_commit();   // unconditional: keeps wait_group(1) counting correct

        const int cur = c % STAGES;
        const uint32_t aBase = sA[cur] + (wm * 64 + lm_row) * SROW + lm_col;
        const uint32_t bBase = sB[cur] + (wn * 64 + lm_row) * SROW + lm_col;

#pragma unroll
        for (int ks = 0; ks < 2; ++ks) {
            uint32_t af[4][4];
            uint32_t bf[4][4];
#pragma unroll
            for (int mf = 0; mf < 4; ++mf)
                ldsm_x4(af[mf], aBase + mf * (16 * SROW) + ks * 32);
#pragma unroll
            for (int nf2 = 0; nf2 < 4; ++nf2)
                ldsm_x4(bf[nf2], bBase + nf2 * (16 * SROW) + ks * 32);
#pragma unroll
            for (int mf = 0; mf < 4; ++mf)
#pragma unroll
                for (int nf = 0; nf < 8; ++nf) {
                    // B pairing: n-half h = nf&1 -> regs {h, h+2} = {k0-7, k8-15}
                    const int g = nf >> 1, h = nf & 1;
                    mma_16816(acc[mf][nf], af[mf], bf[g][h], bf[g][h + 2]);
                }
        }
        BAR_TENSOR();
    }

    // Epilogue: direct STG, float2 per (frag, row-half).
    const int row0 = m_tile * CTA_M + wm * 64 + (lid >> 2);
    const int col0 = n_tile * CTA_N + wn * 64 + (lid & 3) * 2;
#pragma unroll
    for (int mf = 0; mf < 4; ++mf) {
#pragma unroll
        for (int nf = 0; nf < 8; ++nf) {
            float* p0 = out + (size_t)(row0 + mf * 16) * DOUT + col0 + nf * 8;
            float* p1 = p0 + 8 * DOUT;
            *(float2*)p0 = make_float2(acc[mf][nf][0], acc[mf][nf][1]);
            *(float2*)p1 = make_float2(acc[mf][nf][2], acc[mf][nf][3]);
        }
    }
#undef ISSUE_STAGE
}

// ---------------- launch ------------------------------------------------------

extern "C" void kernel_launch(void* const* d_in, const int* in_sizes, int n_in,
                              void* d_out, int out_size) {
    (void)in_sizes; (void)n_in; (void)out_size;
    const float* inp = (const float*)d_in[0];
    const float* w   = (const float*)d_in[1];
    float* out       = (float*)d_out;

    // Expert 0 conversion (A rows 0-2047, B rows 0-4095) + counter reset.
    conv0_kernel<<<6144, 256>>>(inp, w);

    cudaFuncSetAttribute(gemm_kernel,
                         cudaFuncAttributeMaxDynamicSharedMemorySize,
                         SMEM_BYTES);
    gemm_kernel<<<(T_TOK / CTA_M) * (DOUT / CTA_N), THREADS_TOT, SMEM_BYTES>>>(
        inp, w, out);
}

// round 10
// speedup vs baseline: 1.2136x; 1.2136x over previous
#include <cuda_runtime.h>
#include <cuda_fp16.h>
#include <cstdint>

// ----------------------------------------------------------------------------
// GroupedLinear: out[t,n] = sum_k inp[t,k] * weight[e,n,k],  e = t / 2048
// Base-ISA path (no tcgen05 on plain sm_103 target).
// R8 finding: any warp count >8 caps regs at ~170 (3 warps on one SMSP) ->
// accumulator spills; in-kernel converter warps are structurally dead.
// R9: FUSE fp32->fp16 conversion into the GEMM operand path. cp.async loads
// fp32 tiles straight from inputs; fragments assembled by LDS.64 + cvt
// (SROW=160 -> bank-conflict-free). No scratch, no conv kernels, 1 launch.
// GEMM: mma.sync.m16n8k16.f16, 3-stage cp.async pipeline, 8 warps, 64x64/warp.
// ----------------------------------------------------------------------------

#define E_EXPERTS 8
#define DIN 4096
#define DOUT 4096
#define T_TOK 16384
#define GROWB (DIN * 4)        // 16384 bytes per fp32 input row

#define CTA_M 256
#define CTA_N 128
#define NCHUNKS 128            // 4096 / 32 K-chunks
#define THREADS 256
#define STAGES 3

#define SROW 160                                // fp32 tile row stride (128B data + 32 pad)
#define A_STAGE_BYTES (CTA_M * SROW)            // 40960
#define B_STAGE_BYTES (CTA_N * SROW)            // 20480
#define STAGE_BYTES (A_STAGE_BYTES + B_STAGE_BYTES)  // 61440
#define SMEM_BYTES (STAGES * STAGE_BYTES)       // 184320

// ---------------- low-level helpers -----------------------------------------

__device__ __forceinline__ uint32_t smem_to_u32(const void* smem_ptr) {
    uint32_t addr;
    asm("{ .reg .u64 tmp; cvta.to.shared.u64 tmp, %1; cvt.u32.u64 %0, tmp; }"
        : "=r"(addr) : "l"(smem_ptr));
    return addr;
}

__device__ __forceinline__ void cp16(uint32_t s, const void* g) {
    asm volatile("cp.async.cg.shared.global [%0], [%1], 16;"
                 :: "r"(s), "l"(g) : "memory");
}
__device__ __forceinline__ void cp_commit() {
    asm volatile("cp.async.commit_group;" ::: "memory");
}
#define CP_WAIT(n) asm volatile("cp.async.wait_group %0;" :: "n"(n) : "memory")

// Load 2 consecutive fp32 from smem, convert+pack to half2 {lo=k, hi=k+1}.
__device__ __forceinline__ uint32_t lds_cvt(uint32_t addr) {
    float lo, hi;
    asm volatile("ld.shared.v2.f32 {%0,%1}, [%2];"
                 : "=f"(lo), "=f"(hi) : "r"(addr));
    uint32_t r;
    asm("cvt.rn.f16x2.f32 %0, %1, %2;" : "=r"(r) : "f"(hi), "f"(lo));
    return r;
}

__device__ __forceinline__ void mma_16816(float* d, const uint32_t* a,
                                          uint32_t b0, uint32_t b1) {
    asm volatile(
        "mma.sync.aligned.m16n8k16.row.col.f32.f16.f16.f32 "
        "{%0,%1,%2,%3}, {%4,%5,%6,%7}, {%8,%9}, {%0,%1,%2,%3};"
        : "+f"(d[0]), "+f"(d[1]), "+f"(d[2]), "+f"(d[3])
        : "r"(a[0]), "r"(a[1]), "r"(a[2]), "r"(a[3]), "r"(b0), "r"(b1));
}

// ---------------- GEMM kernel (fused conversion) -----------------------------

__global__ void __launch_bounds__(THREADS, 1) gemm_kernel(
    const float* __restrict__ inp, const float* __restrict__ w,
    float* __restrict__ out)
{
    extern __shared__ char smem[];
    const uint32_t smem_u32 = smem_to_u32(smem);
    const int tid = threadIdx.x;
    const int wid = tid >> 5;
    const int lid = tid & 31;

    // Tile decode: N-fastest so concurrent CTAs share A strips + expert B in L2
    const int bx = blockIdx.x;
    const int n_tile = bx & 31;           // 32 N-tiles of 128
    const int m_tile = bx >> 5;           // 64 M-tiles of 256
    const int e = m_tile >> 3;            // 2048 tokens / 256 rows = 8 m-tiles

    const char* Abase = (const char*)(inp + (size_t)(m_tile * CTA_M) * DIN);
    const char* Bbase = (const char*)(w + ((size_t)e * DOUT +
                                           (size_t)n_tile * CTA_N) * DIN);

    uint32_t sA[STAGES], sB[STAGES];
#pragma unroll
    for (int s = 0; s < STAGES; ++s) {
        sA[s] = smem_u32 + s * STAGE_BYTES;
        sB[s] = sA[s] + A_STAGE_BYTES;
    }

    // fp32 chunk = 128B per row. A: 256 rows x 8 x 16B = 2048 cp (8/thread);
    // B: 128 rows x 8 x 16B = 1024 cp (4/thread).
#define ISSUE_STAGE(stg, c) do {                                              \
        const char* aG_ = Abase + (size_t)(c) * 128;                          \
        const char* bG_ = Bbase + (size_t)(c) * 128;                          \
        _Pragma("unroll")                                                     \
        for (int i_ = 0; i_ < 8; ++i_) {                                      \
            int idx_ = tid + i_ * THREADS;                                    \
            int row_ = idx_ >> 3, seg_ = (idx_ & 7) * 16;                     \
            cp16(sA[stg] + row_ * SROW + seg_,                                \
                 aG_ + (size_t)row_ * GROWB + seg_);                          \
        }                                                                     \
        _Pragma("unroll")                                                     \
        for (int i_ = 0; i_ < 4; ++i_) {                                      \
            int idx_ = tid + i_ * THREADS;                                    \
            int row_ = idx_ >> 3, seg_ = (idx_ & 7) * 16;                     \
            cp16(sB[stg] + row_ * SROW + seg_,                                \
                 bG_ + (size_t)row_ * GROWB + seg_);                          \
        }                                                                     \
    } while (0)

    // Warp layout: 4(M) x 2(N); warp tile 64x64.
    const int wm = wid >> 1;
    const int wn = wid & 1;

    // Per-lane fragment base: row (lid>>2), k-offset (lid&3)*2 fp32 = *8 bytes.
    const int fr_row = lid >> 2;
    const int fr_kb  = (lid & 3) * 8;

    float acc[4][8][4];
#pragma unroll
    for (int i = 0; i < 4; ++i)
#pragma unroll
        for (int j = 0; j < 8; ++j)
#pragma unroll
            for (int q = 0; q < 4; ++q) acc[i][j][q] = 0.0f;

    // Prologue: issue 2 stages
    ISSUE_STAGE(0, 0); cp_commit();
    ISSUE_STAGE(1, 1); cp_commit();

#pragma unroll 1
    for (int c = 0; c < NCHUNKS; ++c) {
        CP_WAIT(1);
        __syncthreads();

        if (c + 2 < NCHUNKS) {
            int stg = (c + 2) % STAGES;
            ISSUE_STAGE(stg, c + 2);
        }
        cp_commit();   // unconditional: keeps wait_group(1) counting correct

        const int cur = c % STAGES;
        const uint32_t aBase = sA[cur] + (wm * 64 + fr_row) * SROW + fr_kb;
        const uint32_t bBase = sB[cur] + (wn * 64 + fr_row) * SROW + fr_kb;

#pragma unroll
        for (int ks = 0; ks < 2; ++ks) {
            // A fragments: a0=(g,c0) a1=(g+8,c0) a2=(g,c0+8) a3=(g+8,c0+8)
            uint32_t af[4][4];
#pragma unroll
            for (int mf = 0; mf < 4; ++mf) {
                const uint32_t ab = aBase + mf * (16 * SROW) + ks * 64;
                af[mf][0] = lds_cvt(ab);
                af[mf][1] = lds_cvt(ab + 8 * SROW);
                af[mf][2] = lds_cvt(ab + 32);
                af[mf][3] = lds_cvt(ab + 8 * SROW + 32);
            }
            // B fragments: b0=(n,c0) b1=(n,c0+8), n-block nf of 8 rows
            uint32_t bf[8][2];
#pragma unroll
            for (int nf = 0; nf < 8; ++nf) {
                const uint32_t bb = bBase + nf * (8 * SROW) + ks * 64;
                bf[nf][0] = lds_cvt(bb);
                bf[nf][1] = lds_cvt(bb + 32);
            }
#pragma unroll
            for (int mf = 0; mf < 4; ++mf)
#pragma unroll
                for (int nf = 0; nf < 8; ++nf)
                    mma_16816(acc[mf][nf], af[mf], bf[nf][0], bf[nf][1]);
        }
        __syncthreads();
    }

    // Epilogue: direct STG, float2 per (frag, row-half).
    const int row0 = m_tile * CTA_M + wm * 64 + (lid >> 2);
    const int col0 = n_tile * CTA_N + wn * 64 + (lid & 3) * 2;
#pragma unroll
    for (int mf = 0; mf < 4; ++mf) {
#pragma unroll
        for (int nf = 0; nf < 8; ++nf) {
            float* p0 = out + (size_t)(row0 + mf * 16) * DOUT + col0 + nf * 8;
            float* p1 = p0 + 8 * DOUT;
            *(float2*)p0 = make_float2(acc[mf][nf][0], acc[mf][nf][1]);
            *(float2*)p1 = make_float2(acc[mf][nf][2], acc[mf][nf][3]);
        }
    }
#undef ISSUE_STAGE
}

// ---------------- launch ------------------------------------------------------

extern "C" void kernel_launch(void* const* d_in, const int* in_sizes, int n_in,
                              void* d_out, int out_size) {
    (void)in_sizes; (void)n_in; (void)out_size;
    const float* inp = (const float*)d_in[0];
    const float* w   = (const float*)d_in[1];
    float* out       = (float*)d_out;

    cudaFuncSetAttribute(gemm_kernel,
                         cudaFuncAttributeMaxDynamicSharedMemorySize,
                         SMEM_BYTES);
    gemm_kernel<<<(T_TOK / CTA_M) * (DOUT / CTA_N), THREADS, SMEM_BYTES>>>(
        inp, w, out);
}

// round 11
// speedup vs baseline: 1.3382x; 1.1026x over previous
#include <cuda_runtime.h>
#include <cuda_fp16.h>
#include <cstdint>

// ----------------------------------------------------------------------------
// GroupedLinear: out[t,n] = sum_k inp[t,k] * weight[e,n,k],  e = t / 2048
// Base-ISA path (no tcgen05 on plain sm_103 target).
// R10: fused fp32->fp16 GEMM at 2133 cyc/chunk vs 2048 MMA floor; the gap is
// the post-__syncthreads fragment-load bubble (~60-85 cyc/chunk).
// R11: software-pipeline fragments ACROSS the barrier: preload next chunk's
// ks0 frags right after CP_WAIT(1)+bar, overlap with ks1 MMAs; one bar/chunk.
// GEMM: mma.sync.m16n8k16.f16, 3-stage cp.async pipeline, 8 warps, 64x64/warp.
// ----------------------------------------------------------------------------

#define E_EXPERTS 8
#define DIN 4096
#define DOUT 4096
#define T_TOK 16384
#define GROWB (DIN * 4)        // 16384 bytes per fp32 input row

#define CTA_M 256
#define CTA_N 128
#define NCHUNKS 128            // 4096 / 32 K-chunks
#define THREADS 256
#define STAGES 3

#define SROW 160                                // fp32 tile row stride (128B data + 32 pad)
#define A_STAGE_BYTES (CTA_M * SROW)            // 40960
#define B_STAGE_BYTES (CTA_N * SROW)            // 20480
#define STAGE_BYTES (A_STAGE_BYTES + B_STAGE_BYTES)  // 61440
#define SMEM_BYTES (STAGES * STAGE_BYTES)       // 184320

// ---------------- low-level helpers -----------------------------------------

__device__ __forceinline__ uint32_t smem_to_u32(const void* smem_ptr) {
    uint32_t addr;
    asm("{ .reg .u64 tmp; cvta.to.shared.u64 tmp, %1; cvt.u32.u64 %0, tmp; }"
        : "=r"(addr) : "l"(smem_ptr));
    return addr;
}

__device__ __forceinline__ void cp16(uint32_t s, const void* g) {
    asm volatile("cp.async.cg.shared.global [%0], [%1], 16;"
                 :: "r"(s), "l"(g) : "memory");
}
__device__ __forceinline__ void cp_commit() {
    asm volatile("cp.async.commit_group;" ::: "memory");
}
#define CP_WAIT(n) asm volatile("cp.async.wait_group %0;" :: "n"(n) : "memory")

// Load 2 consecutive fp32 from smem, convert+pack to half2 {lo=k, hi=k+1}.
__device__ __forceinline__ uint32_t lds_cvt(uint32_t addr) {
    float lo, hi;
    asm volatile("ld.shared.v2.f32 {%0,%1}, [%2];"
                 : "=f"(lo), "=f"(hi) : "r"(addr));
    uint32_t r;
    asm("cvt.rn.f16x2.f32 %0, %1, %2;" : "=r"(r) : "f"(hi), "f"(lo));
    return r;
}

__device__ __forceinline__ void mma_16816(float* d, const uint32_t* a,
                                          uint32_t b0, uint32_t b1) {
    asm volatile(
        "mma.sync.aligned.m16n8k16.row.col.f32.f16.f16.f32 "
        "{%0,%1,%2,%3}, {%4,%5,%6,%7}, {%8,%9}, {%0,%1,%2,%3};"
        : "+f"(d[0]), "+f"(d[1]), "+f"(d[2]), "+f"(d[3])
        : "r"(a[0]), "r"(a[1]), "r"(a[2]), "r"(a[3]), "r"(b0), "r"(b1));
}

// ---------------- GEMM kernel (fused conversion, pipelined frags) ------------

__global__ void __launch_bounds__(THREADS, 1) gemm_kernel(
    const float* __restrict__ inp, const float* __restrict__ w,
    float* __restrict__ out)
{
    extern __shared__ char smem[];
    const uint32_t smem_u32 = smem_to_u32(smem);
    const int tid = threadIdx.x;
    const int wid = tid >> 5;
    const int lid = tid & 31;

    // Tile decode: N-fastest so concurrent CTAs share A strips + expert B in L2
    const int bx = blockIdx.x;
    const int n_tile = bx & 31;           // 32 N-tiles of 128
    const int m_tile = bx >> 5;           // 64 M-tiles of 256
    const int e = m_tile >> 3;            // 2048 tokens / 256 rows = 8 m-tiles

    const char* Abase = (const char*)(inp + (size_t)(m_tile * CTA_M) * DIN);
    const char* Bbase = (const char*)(w + ((size_t)e * DOUT +
                                           (size_t)n_tile * CTA_N) * DIN);

    uint32_t sA[STAGES], sB[STAGES];
#pragma unroll
    for (int s = 0; s < STAGES; ++s) {
        sA[s] = smem_u32 + s * STAGE_BYTES;
        sB[s] = sA[s] + A_STAGE_BYTES;
    }

    // fp32 chunk = 128B per row. A: 2048 cp (8/thread); B: 1024 cp (4/thread).
#define ISSUE_STAGE(stg, c) do {                                              \
        const char* aG_ = Abase + (size_t)(c) * 128;                          \
        const char* bG_ = Bbase + (size_t)(c) * 128;                          \
        _Pragma("unroll")                                                     \
        for (int i_ = 0; i_ < 8; ++i_) {                                      \
            int idx_ = tid + i_ * THREADS;                                    \
            int row_ = idx_ >> 3, seg_ = (idx_ & 7) * 16;                     \
            cp16(sA[stg] + row_ * SROW + seg_,                                \
                 aG_ + (size_t)row_ * GROWB + seg_);                          \
        }                                                                     \
        _Pragma("unroll")                                                     \
        for (int i_ = 0; i_ < 4; ++i_) {                                      \
            int idx_ = tid + i_ * THREADS;                                    \
            int row_ = idx_ >> 3, seg_ = (idx_ & 7) * 16;                     \
            cp16(sB[stg] + row_ * SROW + seg_,                                \
                 bG_ + (size_t)row_ * GROWB + seg_);                          \
        }                                                                     \
    } while (0)

    // Warp layout: 4(M) x 2(N); warp tile 64x64.
    const int wm = wid >> 1;
    const int wn = wid & 1;

    // Per-lane fragment base: row (lid>>2), k-offset (lid&3)*2 fp32 = *8 bytes.
    const int fr_row = lid >> 2;
    const int fr_kb  = (lid & 3) * 8;
    const uint32_t aOff = (wm * 64 + fr_row) * SROW + fr_kb;
    const uint32_t bOff = (wn * 64 + fr_row) * SROW + fr_kb;

    // Fragment loaders: ks selects the 16-wide k-half pair offset (0 or 64B).
#define LOAD_A_FRAGS(af, stageA, ksb) do {                                    \
        const uint32_t ab0_ = (stageA) + aOff + (ksb);                        \
        _Pragma("unroll")                                                     \
        for (int mf_ = 0; mf_ < 4; ++mf_) {                                   \
            const uint32_t ab_ = ab0_ + mf_ * (16 * SROW);                    \
            (af)[mf_][0] = lds_cvt(ab_);                                      \
            (af)[mf_][1] = lds_cvt(ab_ + 8 * SROW);                           \
            (af)[mf_][2] = lds_cvt(ab_ + 32);                                 \
            (af)[mf_][3] = lds_cvt(ab_ + 8 * SROW + 32);                      \
        }                                                                     \
    } while (0)
#define LOAD_B_FRAGS(bf, stageB, ksb) do {                                    \
        const uint32_t bb0_ = (stageB) + bOff + (ksb);                        \
        _Pragma("unroll")                                                     \
        for (int nf_ = 0; nf_ < 8; ++nf_) {                                   \
            const uint32_t bb_ = bb0_ + nf_ * (8 * SROW);                     \
            (bf)[nf_][0] = lds_cvt(bb_);                                      \
            (bf)[nf_][1] = lds_cvt(bb_ + 32);                                 \
        }                                                                     \
    } while (0)
#define DO_MMAS(af, bf) do {                                                  \
        _Pragma("unroll")                                                     \
        for (int mf_ = 0; mf_ < 4; ++mf_)                                     \
            _Pragma("unroll")                                                 \
            for (int nf_ = 0; nf_ < 8; ++nf_)                                 \
                mma_16816(acc[mf_][nf_], (af)[mf_], (bf)[nf_][0],             \
                          (bf)[nf_][1]);                                      \
    } while (0)

    float acc[4][8][4];
#pragma unroll
    for (int i = 0; i < 4; ++i)
#pragma unroll
        for (int j = 0; j < 8; ++j)
#pragma unroll
            for (int q = 0; q < 4; ++q) acc[i][j][q] = 0.0f;

    uint32_t af0[4][4], bf0[8][2];   // ks0 frags (preloaded across barrier)
    uint32_t af1[4][4], bf1[8][2];   // ks1 frags

    // Prologue: issue chunks 0,1; wait chunk 0; preload its ks0 frags.
    ISSUE_STAGE(0, 0); cp_commit();
    ISSUE_STAGE(1, 1); cp_commit();
    CP_WAIT(1);
    __syncthreads();
    LOAD_A_FRAGS(af0, sA[0], 0);
    LOAD_B_FRAGS(bf0, sB[0], 0);

#pragma unroll 1
    for (int c = 0; c < NCHUNKS; ++c) {
        const int cur = c % STAGES;
        // Issue chunk c+2 into stage (c+2)%3 = chunk c-1's stage: all its
        // readers finished before the bar of iter c-1, which we have passed.
        if (c + 2 < NCHUNKS) ISSUE_STAGE((c + 2) % STAGES, c + 2);
        cp_commit();   // unconditional: keeps group counting correct

        // ks1 frags of current chunk, then ks0 MMAs (frags already in regs).
        LOAD_A_FRAGS(af1, sA[cur], 64);
        LOAD_B_FRAGS(bf1, sB[cur], 64);
        DO_MMAS(af0, bf0);

        // Outstanding groups {c+1, c+2}: wait until <=1 pending -> c+1 ready.
        CP_WAIT(1);
        __syncthreads();

        // Preload next chunk's ks0 frags; ks1 MMAs cover the LDS latency.
        if (c + 1 < NCHUNKS) {
            const int nxt = (c + 1) % STAGES;
            LOAD_A_FRAGS(af0, sA[nxt], 0);
            LOAD_B_FRAGS(bf0, sB[nxt], 0);
        }
        DO_MMAS(af1, bf1);
    }

    // Epilogue: direct STG, float2 per (frag, row-half).
    const int row0 = m_tile * CTA_M + wm * 64 + (lid >> 2);
    const int col0 = n_tile * CTA_N + wn * 64 + (lid & 3) * 2;
#pragma unroll
    for (int mf = 0; mf < 4; ++mf) {
#pragma unroll
        for (int nf = 0; nf < 8; ++nf) {
            float* p0 = out + (size_t)(row0 + mf * 16) * DOUT + col0 + nf * 8;
            float* p1 = p0 + 8 * DOUT;
            *(float2*)p0 = make_float2(acc[mf][nf][0], acc[mf][nf][1]);
            *(float2*)p1 = make_float2(acc[mf][nf][2], acc[mf][nf][3]);
        }
    }
#undef ISSUE_STAGE
#undef LOAD_A_FRAGS
#undef LOAD_B_FRAGS
#undef DO_MMAS
}

// ---------------- launch ------------------------------------------------------

extern "C" void kernel_launch(void* const* d_in, const int* in_sizes, int n_in,
                              void* d_out, int out_size) {
    (void)in_sizes; (void)n_in; (void)out_size;
    const float* inp = (const float*)d_in[0];
    const float* w   = (const float*)d_in[1];
    float* out       = (float*)d_out;

    cudaFuncSetAttribute(gemm_kernel,
                         cudaFuncAttributeMaxDynamicSharedMemorySize,
                         SMEM_BYTES);
    gemm_kernel<<<(T_TOK / CTA_M) * (DOUT / CTA_N), THREADS, SMEM_BYTES>>>(
        inp, w, out);
}